// round 15
// baseline (speedup 1.0000x reference)
#include <cuda_runtime.h>
#include <cuda_bf16.h>
#include <math.h>
#include <stdint.h>

#define NCH 8
#define GD 96
#define PD 48
#define PVOL (PD*PD*PD)
#define ND 46
#define NACC (82*64)

#define FT 512
#define BSZ 54
#define NTRI (BSZ*(BSZ+1)/2)   // 1485
#define NPER 3

#define NROWS 96
#define ROWB 128               // bytes per smem row (64 bf16)
#define NTILE 33               // lower-triangle 16x8 tiles with col<=55

static __device__ __nv_bfloat16 g_lah[NCH*PVOL];
static __device__ __nv_bfloat16 g_prh[NCH*PVOL];
static __device__ __nv_bfloat16 g_prl[NCH*PVOL];
static __device__ double g_acc[NCH*NACC];

// ---------------------------------------------------------------------------
__device__ __forceinline__ uint32_t smem_u32(const void* p) {
    uint32_t a;
    asm("{ .reg .u64 t; cvta.to.shared.u64 t, %1; cvt.u32.u64 %0, t; }" : "=r"(a) : "l"(p));
    return a;
}
__device__ __forceinline__ void ldsm_x4(uint32_t& r0, uint32_t& r1,
                                        uint32_t& r2, uint32_t& r3, uint32_t addr) {
    asm volatile("ldmatrix.sync.aligned.m8n8.x4.shared.b16 {%0,%1,%2,%3}, [%4];"
                 : "=r"(r0), "=r"(r1), "=r"(r2), "=r"(r3) : "r"(addr));
}
__device__ __forceinline__ void ldsm_x2(uint32_t& r0, uint32_t& r1, uint32_t addr) {
    asm volatile("ldmatrix.sync.aligned.m8n8.x2.shared.b16 {%0,%1}, [%2];"
                 : "=r"(r0), "=r"(r1) : "r"(addr));
}
__device__ __forceinline__ void mma_bf16(float* d, uint32_t a0, uint32_t a1,
                                         uint32_t a2, uint32_t a3,
                                         uint32_t b0, uint32_t b1) {
    asm volatile(
        "mma.sync.aligned.m16n8k16.row.col.f32.bf16.bf16.f32 "
        "{%0,%1,%2,%3}, {%4,%5,%6,%7}, {%8,%9}, {%0,%1,%2,%3};"
        : "+f"(d[0]), "+f"(d[1]), "+f"(d[2]), "+f"(d[3])
        : "r"(a0), "r"(a1), "r"(a2), "r"(a3), "r"(b0), "r"(b1));
}
__device__ __forceinline__ void tile_of(int n, int& ti, int& tj) {
    // tj <= min(2*ti+1, 6); counts per ti: 2,4,6,7,7,7
    if (n < 2)       { ti = 0; tj = n; }
    else if (n < 6)  { ti = 1; tj = n - 2; }
    else if (n < 12) { ti = 2; tj = n - 6; }
    else if (n < 19) { ti = 3; tj = n - 12; }
    else if (n < 26) { ti = 4; tj = n - 19; }
    else             { ti = 5; tj = n - 26; }
}

// ---------------------------------------------------------------------------
__global__ void pool_kernel(const float* __restrict__ logits,
                            const int* __restrict__ labels, float* out) {
    int idx = blockIdx.x * blockDim.x + threadIdx.x;
    if (idx < NCH*NACC) g_acc[idx] = 0.0;
    if (idx == 0) out[0] = 0.0f;
    if (idx >= NCH*PVOL) return;
    int ch  = idx / PVOL;
    int rem = idx - ch * PVOL;
    int p0 = rem / (PD*PD), p1 = (rem / PD) % PD, p2 = rem % PD;
    int n = ch >> 2, c = ch & 3;
    const float* lg = logits + (size_t)ch * GD*GD*GD;
    const int*   lb = labels + (size_t)n  * GD*GD*GD;

    float la = 0.f, pr = 0.f;
    #pragma unroll
    for (int d0 = 0; d0 < 2; d0++)
        #pragma unroll
        for (int d1 = 0; d1 < 2; d1++) {
            int base = ((2*p0 + d0) * GD + (2*p1 + d1)) * GD + 2*p2;
            float2 lv = *reinterpret_cast<const float2*>(lg + base);
            int2   bv = *reinterpret_cast<const int2*>(lb + base);
            { bool m = (bv.x < 4); if (m && bv.x == c) la = 1.f;
              float s = 1.f / (1.f + expf(-lv.x));
              pr = fmaxf(pr, (m ? s : 0.f) + 1e-6f); }
            { bool m = (bv.y < 4); if (m && bv.y == c) la = 1.f;
              float s = 1.f / (1.f + expf(-lv.y));
              pr = fmaxf(pr, (m ? s : 0.f) + 1e-6f); }
        }
    __nv_bfloat16 ph = __float2bfloat16(pr);
    g_lah[idx] = __float2bfloat16(la);
    g_prh[idx] = ph;
    g_prl[idx] = __float2bfloat16(pr - __bfloat162float(ph));
}

// ---------------------------------------------------------------------------
// Gram via HMMA self-product. Block = (z0, ch), 256 threads / 8 warps.
// Smem tile: 96 rows x 64 bf16, swizzle: byte ^ ((row&7)<<4).
// Rows: 0-26 la, 27-53 prh, 54 ones, 55-81 prl, 82-95 zero. B = A (aliased).
__global__ __launch_bounds__(256) void gram_hmma_kernel() {
    __shared__ __align__(1024) __nv_bfloat16 As[NROWS*64];   // 12 KB
    int ch = blockIdx.y;
    int z0 = blockIdx.x;          // 0..45
    int t = threadIdx.x;
    int wid = t >> 5, lane = t & 31;
    uint32_t base = smem_u32(As);

    // zero tile (pad cols 46-63 and rows 82-95 stay zero forever)
    for (int i = t; i < NROWS*64/2; i += 256)
        reinterpret_cast<uint32_t*>(As)[i] = 0u;
    __syncthreads();
    // ones row 54, k=0..45 (written once; swizzled)
    if (t < 23) {
        __nv_bfloat162 one2 = __floats2bfloat162_rn(1.f, 1.f);
        uint32_t off = ((uint32_t)(t*4)) ^ ((54u & 7u) << 4);
        *reinterpret_cast<__nv_bfloat162*>(reinterpret_cast<char*>(As) + 54*ROWB + off) = one2;
    }

    // build-row setup (threads 0..81 except 54)
    bool bld = (t < 82) && (t != 54);
    const __nv_bfloat16* fld = g_lah + (size_t)ch*PVOL;
    int q = 0;
    if (t < 27)                 { q = t; }
    else if (t < 54)            { fld = g_prh + (size_t)ch*PVOL; q = t - 27; }
    else if (t >= 55 && t < 82) { fld = g_prl + (size_t)ch*PVOL; q = t - 55; }
    int zs = q / 9, ys = (q / 3) % 3, xs = q % 3;
    const __nv_bfloat16* fbase = fld + ((size_t)(z0 + zs) * PD) * PD + xs;
    uint32_t swx = (uint32_t)((t & 7) << 4);
    char* rp = reinterpret_cast<char*>(As) + t*ROWB;

    // per-warp tiles and accumulators
    int myT[5]; int nT = 0;
    for (int n = wid; n < NTILE; n += 8) myT[nT++] = n;
    float acc[5][4];
    #pragma unroll
    for (int m = 0; m < 5; m++)
        #pragma unroll
        for (int u = 0; u < 4; u++) acc[m][u] = 0.f;

    for (int c = 0; c < 46; c++) {
        if (bld) {
            const __nv_bfloat16* src = fbase + (size_t)(c + ys) * PD;
            #pragma unroll
            for (int i = 0; i < 23; i++) {
                int k = 2*i;
                __nv_bfloat162 pv;
                pv.x = src[k]; pv.y = src[k + 1];
                *reinterpret_cast<__nv_bfloat162*>(rp + (((uint32_t)(4*i)) ^ swx)) = pv;
            }
        }
        __syncthreads();

        for (int m = 0; m < nT; m++) {
            int ti, tj; tile_of(myT[m], ti, tj);
            #pragma unroll
            for (int ks = 0; ks < 4; ks++) {
                int k0 = ks * 16;
                // A fragment: rows 16ti..16ti+15, k cols k0..k0+15
                int ra = ti*16 + (lane & 15);
                uint32_t cbA = (uint32_t)(((lane >> 4) << 4) + k0*2);
                uint32_t aaddr = base + (uint32_t)ra*ROWB + (cbA ^ ((uint32_t)(ra & 7) << 4));
                uint32_t a0, a1, a2, a3;
                ldsm_x4(a0, a1, a2, a3, aaddr);
                // B fragment: n-rows 8tj..8tj+7, k cols k0..k0+15 (NO trans:
                // [n][k] row storage already matches the col-major B fragment)
                int rb = tj*8 + (lane & 7);
                uint32_t cbB = (uint32_t)(k0*2 + ((lane & 8) ? 16 : 0));
                uint32_t baddr = base + (uint32_t)rb*ROWB + (cbB ^ ((uint32_t)(rb & 7) << 4));
                uint32_t b0, b1;
                ldsm_x2(b0, b1, baddr);
                mma_bf16(acc[m], a0, a1, a2, a3, b0, b1);
            }
        }
        __syncthreads();
    }

    // flush: fp64 atomics into g_acc (rows < 82, cols < 56)
    double* A = g_acc + (size_t)ch * NACC;
    for (int m = 0; m < nT; m++) {
        int ti, tj; tile_of(myT[m], ti, tj);
        int R0 = ti*16 + (lane >> 2);
        int C0 = tj*8 + 2*(lane & 3);
        if (R0 < 82) {
            atomicAdd(&A[R0*64 + C0], (double)acc[m][0]);
            atomicAdd(&A[R0*64 + C0 + 1], (double)acc[m][1]);
        }
        if (R0 + 8 < 82) {
            atomicAdd(&A[(R0+8)*64 + C0], (double)acc[m][2]);
            atomicAdd(&A[(R0+8)*64 + C0 + 1], (double)acc[m][3]);
        }
    }
}

// --- df64 on the fp32 pipe ---------------------------------------------------
struct df { float h, l; };
__device__ __forceinline__ df df_make(double x) {
    float h = (float)x; float l = (float)(x - (double)h);
    df r; r.h = h; r.l = l; return r;
}
__device__ __forceinline__ df df_add(df a, df b) {
    float s  = __fadd_rn(a.h, b.h);
    float bb = __fsub_rn(s, a.h);
    float e  = __fadd_rn(__fsub_rn(a.h, __fsub_rn(s, bb)), __fsub_rn(b.h, bb));
    e = __fadd_rn(e, __fadd_rn(a.l, b.l));
    float s2 = __fadd_rn(s, e);
    float e2 = __fsub_rn(e, __fsub_rn(s2, s));
    df r; r.h = s2; r.l = e2; return r;
}
__device__ __forceinline__ df df_mul(df a, df b) {
    float p = __fmul_rn(a.h, b.h);
    float e = __fmaf_rn(a.h, b.h, -p);
    e = __fmaf_rn(a.h, b.l, e);
    e = __fmaf_rn(a.l, b.h, e);
    float s2 = __fadd_rn(p, e);
    float e2 = __fsub_rn(e, __fsub_rn(s2, p));
    df r; r.h = s2; r.l = e2; return r;
}
__device__ __forceinline__ df df_neg(df a) { df r; r.h = -a.h; r.l = -a.l; return r; }
__device__ __forceinline__ df df_sub(df a, df b) { return df_add(a, df_neg(b)); }
__device__ __forceinline__ df df_rcp(df d) {
    df iv; iv.h = __frcp_rn(d.h); iv.l = 0.f;
    df two; two.h = 2.0f; two.l = 0.f;
    #pragma unroll
    for (int it = 0; it < 2; it++) iv = df_mul(iv, df_sub(two, df_mul(d, iv)));
    return iv;
}

// ---------------------------------------------------------------------------
// Finalize: head+residual recombination, then Schur-determinant LDL^T (df64).
__global__ __launch_bounds__(FT) void finalize_kernel(float* out) {
    __shared__ float2 A[BSZ*BSZ];
    __shared__ double red;
    int ch = blockIdx.x;
    int tid = threadIdx.x;
    const double* D = g_acc + (size_t)ch * NACC;
    const double invM = 1.0 / (double)(ND*ND*ND);
    const double ALPHA = 0.0005;
    if (tid == 0) red = 0.0;

    #define DD(a, b) D[(a)*64 + (b)]
    for (int e = tid; e < BSZ*BSZ; e += FT) {
        int a = e / BSZ, b = e % BSZ;
        if (b > a) continue;
        double v;
        if (a < 27) {               // pr_a x pr_b
            double Spa = DD(54, 27+a) + DD(55+a, 54);
            double Spb = DD(54, 27+b) + DD(55+b, 54);
            double g = DD(27+a, 27+b) + DD(55+a, 27+b) + DD(55+b, 27+a);
            v = g - Spa*Spb*invM + (a == b ? ALPHA : 0.0);
        } else if (b < 27) {        // la_{a-27} x pr_b
            int i = a - 27;
            double Sli = DD(54, i);
            double Spb = DD(54, 27+b) + DD(55+b, 54);
            v = DD(27+b, i) + DD(55+b, i) - Sli*Spb*invM;
        } else {                    // la-la
            int i = a - 27, q2 = b - 27;
            v = DD(i, q2) - DD(54, i)*DD(54, q2)*invM + (i == q2 ? ALPHA : 0.0);
        }
        df d = df_make(v);
        A[e] = make_float2(d.h, d.l);
    }
    __syncthreads();

    int iB[NPER], qB[NPER], qV[NPER];
    df accv[NPER];
    #pragma unroll
    for (int n = 0; n < NPER; n++) {
        int t = tid + n*FT;
        if (t < NTRI) {
            int i = (int)((sqrtf(8.0f*(float)t + 1.0f) - 1.0f) * 0.5f);
            while ((i+1)*(i+2)/2 <= t) i++;
            while (i*(i+1)/2 > t) i--;
            int q2 = t - i*(i+1)/2;
            iB[n] = i*BSZ; qB[n] = q2*BSZ; qV[n] = q2;
            float2 v = A[i*BSZ + q2];
            accv[n].h = v.x; accv[n].l = v.y;
        } else { iB[n] = 0; qB[n] = 0; qV[n] = -1; accv[n].h = 0.f; accv[n].l = 0.f; }
    }

    for (int k = 0; k < BSZ - 1; k++) {
        float2 dv = A[k*BSZ + k];
        df Dk; Dk.h = dv.x; Dk.l = dv.y;
        df IV = df_rcp(Dk);
        #pragma unroll
        for (int n = 0; n < NPER; n++) {
            if (qV[n] > k) {
                float2 cik = A[iB[n] + k];
                float2 cqk = A[qB[n] + k];
                df Xik; Xik.h = cik.x; Xik.l = cik.y;
                df Xqk; Xqk.h = cqk.x; Xqk.l = cqk.y;
                df w = df_mul(Xik, df_mul(Xqk, IV));
                accv[n] = df_sub(accv[n], w);
                A[iB[n] + qV[n]] = make_float2(accv[n].h, accv[n].l);
            }
        }
        __syncthreads();
    }

    if (tid >= 27 && tid < 54) {
        float2 dv = A[tid*BSZ + tid];
        atomicAdd(&red, log(sqrt((double)dv.x + (double)dv.y) + 1e-8));
    }
    __syncthreads();
    if (tid == 0) atomicAdd(out, (float)(red / 54.0));
}

// ---------------------------------------------------------------------------
extern "C" void kernel_launch(void* const* d_in, const int* in_sizes, int n_in,
                              void* d_out, int out_size) {
    const float* logits = (const float*)d_in[0];
    const int*   labels = (const int*)d_in[1];
    float* out = (float*)d_out;

    pool_kernel<<<(NCH*PVOL + 255)/256, 256>>>(logits, labels, out);
    dim3 g(46, NCH);   // 46 z-slabs x 8 channels = 368 blocks
    gram_hmma_kernel<<<g, 256>>>();
    finalize_kernel<<<NCH, FT>>>(out);
}